// round 4
// baseline (speedup 1.0000x reference)
#include <cuda_runtime.h>
#include <cuda_bf16.h>
#include <cstdint>

// ----------------------------------------------------------------------------
// Round 4: bf16x3 mma.sync GEMM, CTA tile 128x256, warp tile 64x64,
// 5-stage cp.async pipeline. (tcgen05 unavailable: harness targets compute_103.)
//
//   Wf = W + scatter(delta)
//   A  = [hi(x)|hi(x)|lo(x)]   [8192,12288] bf16
//   B  = [hi(W)|lo(W)|hi(W)]   [4096,12288] bf16
//   out = A @ B^T + bias  (fp32 accum)
// ----------------------------------------------------------------------------

#define BM 128
#define BN 256
#define BK 32
#define STAGES 5
#define K3 12288
#define ROW_STRIDE 80                        // 64B data + 16B pad
#define A_STAGE_BYTES (BM * ROW_STRIDE)      // 10240
#define B_STAGE_BYTES (BN * ROW_STRIDE)      // 20480
#define STAGE_BYTES (A_STAGE_BYTES + B_STAGE_BYTES)   // 30720
#define SMEM_TOTAL (STAGES * STAGE_BYTES)    // 153600

__device__ float          g_Wf[4096u * 4096u];
__device__ __nv_bfloat16  g_A[8192u * 12288u];
__device__ __nv_bfloat16  g_B[4096u * 12288u];

// ---------------- helpers ----------------

__device__ __forceinline__ uint32_t smem_u32(const void* p) {
    uint32_t a;
    asm("{ .reg .u64 t; cvta.to.shared.u64 t, %1; cvt.u32.u64 %0, t; }"
        : "=r"(a) : "l"(p));
    return a;
}

__device__ __forceinline__ void cp_async16(uint32_t dst, const void* src) {
    asm volatile("cp.async.cg.shared.global [%0], [%1], 16;"
                 :: "r"(dst), "l"(src) : "memory");
}
#define CP_COMMIT() asm volatile("cp.async.commit_group;" ::: "memory")
#define CP_WAIT(n)  asm volatile("cp.async.wait_group %0;" :: "n"(n) : "memory")

__device__ __forceinline__ void ldmatrix4(uint32_t* r, uint32_t addr) {
    asm volatile("ldmatrix.sync.aligned.m8n8.x4.shared.b16 {%0,%1,%2,%3}, [%4];"
                 : "=r"(r[0]), "=r"(r[1]), "=r"(r[2]), "=r"(r[3]) : "r"(addr));
}

__device__ __forceinline__ void mma16816(float* d, const uint32_t* a,
                                         const uint32_t* b) {
    asm volatile(
        "mma.sync.aligned.m16n8k16.row.col.f32.bf16.bf16.f32 "
        "{%0,%1,%2,%3}, {%4,%5,%6,%7}, {%8,%9}, {%0,%1,%2,%3};"
        : "+f"(d[0]), "+f"(d[1]), "+f"(d[2]), "+f"(d[3])
        : "r"(a[0]), "r"(a[1]), "r"(a[2]), "r"(a[3]), "r"(b[0]), "r"(b[1]));
}

// ---------------- Phase 1 ----------------

__global__ void prep_wcopy_kernel(const float* __restrict__ w, int n4) {
    float4* dst = reinterpret_cast<float4*>(g_Wf);
    const float4* src = reinterpret_cast<const float4*>(w);
    for (int i = blockIdx.x * blockDim.x + threadIdx.x; i < n4;
         i += gridDim.x * blockDim.x)
        dst[i] = src[i];
}

__global__ void prep_scatter_kernel(const float* __restrict__ sw,
                                    const int* __restrict__ rows,
                                    const int* __restrict__ cols,
                                    int nnz, int K) {
    int i = blockIdx.x * blockDim.x + threadIdx.x;
    if (i < nnz)
        atomicAdd(&g_Wf[(size_t)rows[i] * K + cols[i]], sw[i]);
}

__device__ __forceinline__ void split2(float x, float y,
                                       __nv_bfloat162& hi, __nv_bfloat162& lo) {
    __nv_bfloat16 hx = __float2bfloat16_rn(x);
    __nv_bfloat16 hy = __float2bfloat16_rn(y);
    __nv_bfloat16 lx = __float2bfloat16_rn(x - __bfloat162float(hx));
    __nv_bfloat16 ly = __float2bfloat16_rn(y - __bfloat162float(hy));
    hi = __nv_bfloat162(hx, hy);
    lo = __nv_bfloat162(lx, ly);
}

__global__ void prep_wsplit_kernel(int n4, int K) {
    const float4* src = reinterpret_cast<const float4*>(g_Wf);
    const int rowq = K / 4;
    for (int i = blockIdx.x * blockDim.x + threadIdx.x; i < n4;
         i += gridDim.x * blockDim.x) {
        float4 v = src[i];
        int row = i / rowq, col = (i % rowq) * 4;
        __nv_bfloat162 h0, l0, h1, l1;
        split2(v.x, v.y, h0, l0);
        split2(v.z, v.w, h1, l1);
        size_t base = (size_t)row * K3 + col;
        __nv_bfloat162* p0 = reinterpret_cast<__nv_bfloat162*>(&g_B[base]);
        __nv_bfloat162* p1 = reinterpret_cast<__nv_bfloat162*>(&g_B[base + K]);
        __nv_bfloat162* p2 = reinterpret_cast<__nv_bfloat162*>(&g_B[base + 2 * K]);
        p0[0] = h0; p0[1] = h1;
        p1[0] = l0; p1[1] = l1;
        p2[0] = h0; p2[1] = h1;
    }
}

__global__ void prep_xsplit_kernel(const float* __restrict__ x, int n4, int K) {
    const float4* src = reinterpret_cast<const float4*>(x);
    const int rowq = K / 4;
    for (int i = blockIdx.x * blockDim.x + threadIdx.x; i < n4;
         i += gridDim.x * blockDim.x) {
        float4 v = src[i];
        int row = i / rowq, col = (i % rowq) * 4;
        __nv_bfloat162 h0, l0, h1, l1;
        split2(v.x, v.y, h0, l0);
        split2(v.z, v.w, h1, l1);
        size_t base = (size_t)row * K3 + col;
        __nv_bfloat162* p0 = reinterpret_cast<__nv_bfloat162*>(&g_A[base]);
        __nv_bfloat162* p1 = reinterpret_cast<__nv_bfloat162*>(&g_A[base + K]);
        __nv_bfloat162* p2 = reinterpret_cast<__nv_bfloat162*>(&g_A[base + 2 * K]);
        p0[0] = h0; p0[1] = h1;
        p1[0] = h0; p1[1] = h1;
        p2[0] = l0; p2[1] = l1;
    }
}

// ---------------- Phase 2: GEMM ----------------

__device__ __forceinline__ void load_stage(uint32_t stage_base, int tid,
                                           const __nv_bfloat16* gA,
                                           const __nv_bfloat16* gB, int k0) {
    // A: 128 rows x 4 chunks = 512 ops; B: 256 rows x 4 chunks = 1024 ops.
    #pragma unroll
    for (int i = 0; i < 2; i++) {
        int u = i * 256 + tid;
        int row = u >> 2, ch = u & 3;
        cp_async16(stage_base + row * ROW_STRIDE + ch * 16,
                   gA + (size_t)row * K3 + k0 + ch * 8);
    }
    #pragma unroll
    for (int i = 0; i < 4; i++) {
        int u = i * 256 + tid;
        int row = u >> 2, ch = u & 3;
        cp_async16(stage_base + A_STAGE_BYTES + row * ROW_STRIDE + ch * 16,
                   gB + (size_t)row * K3 + k0 + ch * 8);
    }
}

__global__ __launch_bounds__(256, 1)
void gemm_kernel(const float* __restrict__ bias, float* __restrict__ C, int N) {
    extern __shared__ char smem[];
    const uint32_t sbase = smem_u32(smem);

    const int tid = threadIdx.x;
    const int warp = tid >> 5;
    const int lane = tid & 31;
    const int warp_m = warp & 1;     // 2 (m) x 4 (n) warps, each 64x64
    const int warp_n = warp >> 1;

    const int m0 = blockIdx.y * BM;
    const int n0 = blockIdx.x * BN;

    const __nv_bfloat16* gA = g_A + (size_t)m0 * K3;
    const __nv_bfloat16* gB = g_B + (size_t)n0 * K3;

    // ldmatrix per-lane addressing (same fragment mapping as round 3)
    const int a_row = warp_m * 64 + (lane & 15);
    const int a_chb = lane >> 4;
    const int b_row = warp_n * 64 + ((lane >> 4) << 3) + (lane & 7);
    const int b_ch  = (lane >> 3) & 1;

    float acc[4][8][4] = {};   // 128 regs

    #pragma unroll
    for (int s = 0; s < STAGES - 1; s++) {
        load_stage(sbase + s * STAGE_BYTES, tid, gA, gB, s * BK);
        CP_COMMIT();
    }

    const int NT = K3 / BK;   // 384
    for (int kt = 0; kt < NT; kt++) {
        CP_WAIT(STAGES - 2);
        __syncthreads();

        const int pf = kt + STAGES - 1;
        if (pf < NT)
            load_stage(sbase + (pf % STAGES) * STAGE_BYTES, tid, gA, gB, pf * BK);
        CP_COMMIT();

        const uint32_t As = sbase + (kt % STAGES) * STAGE_BYTES;
        const uint32_t Bs = As + A_STAGE_BYTES;

        #pragma unroll
        for (int ks = 0; ks < 2; ks++) {
            uint32_t af[4][4], bf[4][4];
            #pragma unroll
            for (int mi = 0; mi < 4; mi++)
                ldmatrix4(af[mi], As + (a_row + mi * 16) * ROW_STRIDE
                                     + (ks * 2 + a_chb) * 16);
            #pragma unroll
            for (int bi = 0; bi < 4; bi++)
                ldmatrix4(bf[bi], Bs + (b_row + bi * 16) * ROW_STRIDE
                                     + (ks * 2 + b_ch) * 16);
            #pragma unroll
            for (int mi = 0; mi < 4; mi++) {
                #pragma unroll
                for (int ni = 0; ni < 8; ni++)
                    mma16816(acc[mi][ni], af[mi], &bf[ni >> 1][(ni & 1) * 2]);
            }
        }
    }

    // Epilogue
    const int l4 = lane >> 2;
    const int l2 = (lane & 3) * 2;
    #pragma unroll
    for (int ni = 0; ni < 8; ni++) {
        const int col = n0 + warp_n * 64 + ni * 8 + l2;
        const float2 bv = *reinterpret_cast<const float2*>(&bias[col]);
        #pragma unroll
        for (int mi = 0; mi < 4; mi++) {
            const int row = m0 + warp_m * 64 + mi * 16 + l4;
            float2 v0, v1;
            v0.x = acc[mi][ni][0] + bv.x;
            v0.y = acc[mi][ni][1] + bv.y;
            v1.x = acc[mi][ni][2] + bv.x;
            v1.y = acc[mi][ni][3] + bv.y;
            *reinterpret_cast<float2*>(&C[(size_t)row * N + col]) = v0;
            *reinterpret_cast<float2*>(&C[(size_t)(row + 8) * N + col]) = v1;
        }
    }
}

// ---------------- launch ----------------

extern "C" void kernel_launch(void* const* d_in, const int* in_sizes, int n_in,
                              void* d_out, int out_size) {
    const float* x    = (const float*)d_in[0];
    const float* w    = (const float*)d_in[1];
    const float* bias = (const float*)d_in[2];
    const float* sw   = (const float*)d_in[3];
    const int*   idx  = (const int*)d_in[4];
    float* out = (float*)d_out;

    const int N = in_sizes[2];        // 4096
    const int K = in_sizes[1] / N;    // 4096
    const int M = in_sizes[0] / K;    // 8192
    const int nnz = in_sizes[3];      // 262144

    static bool attr_done = false;
    if (!attr_done) {
        cudaFuncSetAttribute(gemm_kernel,
                             cudaFuncAttributeMaxDynamicSharedMemorySize, SMEM_TOTAL);
        attr_done = true;
    }

    prep_wcopy_kernel<<<1024, 256>>>(w, (N * K) / 4);
    prep_scatter_kernel<<<(nnz + 255) / 256, 256>>>(sw, idx, idx + nnz, nnz, K);
    prep_wsplit_kernel<<<1024, 256>>>((N * K) / 4, K);
    prep_xsplit_kernel<<<2048, 256>>>(x, (M / 4) * K, K);

    dim3 grid(N / BN, M / BM);   // (16, 64)
    gemm_kernel<<<grid, 256, SMEM_TOTAL>>>(bias, out, N);
}

// round 5
// speedup vs baseline: 1.2922x; 1.2922x over previous
#include <cuda_runtime.h>
#include <cuda_bf16.h>
#include <cstdint>

// ----------------------------------------------------------------------------
// Round 5: bf16x3 GEMM with fragment-level reuse.
//   A = [hi(x)|lo(x)]  [8192, 8192] bf16    B = [hi(W)|lo(W)]  [4096, 8192]
//   per chunk: acc += Ahi*Bhi + Ahi*Blo + Alo*Bhi   (fp32 accum)
// CTA 128x128 (2 CTAs/SM), warp tile 64x32, BK=32, double-buffered cp.async.
// ----------------------------------------------------------------------------

#define BM 128
#define BN 128
#define BK 32
#define STAGES 2
#define K2 8192
#define ROW_STRIDE 80                         // 64B data + 16B pad
#define TILE_BYTES (128 * ROW_STRIDE)         // 10240 per tile
#define STAGE_BYTES (4 * TILE_BYTES)          // Ahi,Alo,Bhi,Blo = 40960
#define SMEM_TOTAL (STAGES * STAGE_BYTES)     // 81920

__device__ float          g_Wf[4096u * 4096u];          // 64 MB
__device__ __nv_bfloat16  g_A[8192u * 8192u];           // 128 MB
__device__ __nv_bfloat16  g_B[4096u * 8192u];           // 64 MB

// ---------------- helpers ----------------

__device__ __forceinline__ uint32_t smem_u32(const void* p) {
    uint32_t a;
    asm("{ .reg .u64 t; cvta.to.shared.u64 t, %1; cvt.u32.u64 %0, t; }"
        : "=r"(a) : "l"(p));
    return a;
}

__device__ __forceinline__ void cp_async16(uint32_t dst, const void* src) {
    asm volatile("cp.async.cg.shared.global [%0], [%1], 16;"
                 :: "r"(dst), "l"(src) : "memory");
}
#define CP_COMMIT() asm volatile("cp.async.commit_group;" ::: "memory")
#define CP_WAIT(n)  asm volatile("cp.async.wait_group %0;" :: "n"(n) : "memory")

__device__ __forceinline__ void ldmatrix4(uint32_t* r, uint32_t addr) {
    asm volatile("ldmatrix.sync.aligned.m8n8.x4.shared.b16 {%0,%1,%2,%3}, [%4];"
                 : "=r"(r[0]), "=r"(r[1]), "=r"(r[2]), "=r"(r[3]) : "r"(addr));
}

__device__ __forceinline__ void mma16816(float* d, const uint32_t* a,
                                         const uint32_t* b) {
    asm volatile(
        "mma.sync.aligned.m16n8k16.row.col.f32.bf16.bf16.f32 "
        "{%0,%1,%2,%3}, {%4,%5,%6,%7}, {%8,%9}, {%0,%1,%2,%3};"
        : "+f"(d[0]), "+f"(d[1]), "+f"(d[2]), "+f"(d[3])
        : "r"(a[0]), "r"(a[1]), "r"(a[2]), "r"(a[3]), "r"(b[0]), "r"(b[1]));
}

// ---------------- Phase 1 ----------------

__global__ void prep_wcopy_kernel(const float* __restrict__ w, int n4) {
    float4* dst = reinterpret_cast<float4*>(g_Wf);
    const float4* src = reinterpret_cast<const float4*>(w);
    for (int i = blockIdx.x * blockDim.x + threadIdx.x; i < n4;
         i += gridDim.x * blockDim.x)
        dst[i] = src[i];
}

__global__ void prep_scatter_kernel(const float* __restrict__ sw,
                                    const int* __restrict__ rows,
                                    const int* __restrict__ cols,
                                    int nnz, int K) {
    int i = blockIdx.x * blockDim.x + threadIdx.x;
    if (i < nnz)
        atomicAdd(&g_Wf[(size_t)rows[i] * K + cols[i]], sw[i]);
}

__device__ __forceinline__ void split2(float x, float y,
                                       __nv_bfloat162& hi, __nv_bfloat162& lo) {
    __nv_bfloat16 hx = __float2bfloat16_rn(x);
    __nv_bfloat16 hy = __float2bfloat16_rn(y);
    __nv_bfloat16 lx = __float2bfloat16_rn(x - __bfloat162float(hx));
    __nv_bfloat16 ly = __float2bfloat16_rn(y - __bfloat162float(hy));
    hi = __nv_bfloat162(hx, hy);
    lo = __nv_bfloat162(lx, ly);
}

// B row n: [ hi(W) (4096) | lo(W) (4096) ]
__global__ void prep_wsplit_kernel(int n4, int K) {
    const float4* src = reinterpret_cast<const float4*>(g_Wf);
    const int rowq = K / 4;
    for (int i = blockIdx.x * blockDim.x + threadIdx.x; i < n4;
         i += gridDim.x * blockDim.x) {
        float4 v = src[i];
        int row = i / rowq, col = (i % rowq) * 4;
        __nv_bfloat162 h0, l0, h1, l1;
        split2(v.x, v.y, h0, l0);
        split2(v.z, v.w, h1, l1);
        size_t base = (size_t)row * K2 + col;
        __nv_bfloat162* ph = reinterpret_cast<__nv_bfloat162*>(&g_B[base]);
        __nv_bfloat162* pl = reinterpret_cast<__nv_bfloat162*>(&g_B[base + K]);
        ph[0] = h0; ph[1] = h1;
        pl[0] = l0; pl[1] = l1;
    }
}

// A row m: [ hi(x) | lo(x) ]
__global__ void prep_xsplit_kernel(const float* __restrict__ x, int n4, int K) {
    const float4* src = reinterpret_cast<const float4*>(x);
    const int rowq = K / 4;
    for (int i = blockIdx.x * blockDim.x + threadIdx.x; i < n4;
         i += gridDim.x * blockDim.x) {
        float4 v = src[i];
        int row = i / rowq, col = (i % rowq) * 4;
        __nv_bfloat162 h0, l0, h1, l1;
        split2(v.x, v.y, h0, l0);
        split2(v.z, v.w, h1, l1);
        size_t base = (size_t)row * K2 + col;
        __nv_bfloat162* ph = reinterpret_cast<__nv_bfloat162*>(&g_A[base]);
        __nv_bfloat162* pl = reinterpret_cast<__nv_bfloat162*>(&g_A[base + K]);
        ph[0] = h0; ph[1] = h1;
        pl[0] = l0; pl[1] = l1;
    }
}

// ---------------- Phase 2: GEMM ----------------
// Stage layout: [Ahi | Alo | Bhi | Blo], each 128 rows x 80B.

__device__ __forceinline__ void load_stage(uint32_t stage_base, int tid,
                                           const __nv_bfloat16* gA,
                                           const __nv_bfloat16* gB, int k0) {
    #pragma unroll
    for (int t = 0; t < 4; t++) {
        const __nv_bfloat16* src_base = (t < 2) ? gA : gB;
        const int kofs = k0 + (t & 1) * 4096;    // hi at k0, lo at k0+4096
        const uint32_t dbase = stage_base + t * TILE_BYTES;
        #pragma unroll
        for (int i = 0; i < 2; i++) {
            int u = i * 256 + tid;
            int row = u >> 2, ch = u & 3;
            cp_async16(dbase + row * ROW_STRIDE + ch * 16,
                       src_base + (size_t)row * K2 + kofs + ch * 8);
        }
    }
}

__global__ __launch_bounds__(256, 2)
void gemm_kernel(const float* __restrict__ bias, float* __restrict__ C, int N) {
    extern __shared__ char smem[];
    const uint32_t sbase = smem_u32(smem);

    const int tid = threadIdx.x;
    const int warp = tid >> 5;
    const int lane = tid & 31;
    const int warp_m = warp & 1;     // 2 (m) x 4 (n), warp tile 64x32
    const int warp_n = warp >> 1;

    const int m0 = blockIdx.y * BM;
    const int n0 = blockIdx.x * BN;

    const __nv_bfloat16* gA = g_A + (size_t)m0 * K2;
    const __nv_bfloat16* gB = g_B + (size_t)n0 * K2;

    const int a_row = warp_m * 64 + (lane & 15);
    const int a_chb = lane >> 4;
    const int b_row = warp_n * 32 + ((lane >> 4) << 3) + (lane & 7);
    const int b_ch  = (lane >> 3) & 1;

    float acc[4][4][4] = {};   // 64 regs

    load_stage(sbase, tid, gA, gB, 0);
    CP_COMMIT();

    const int NT = 4096 / BK;   // 128 chunks
    for (int kt = 0; kt < NT; kt++) {
        CP_WAIT(0);
        __syncthreads();

        if (kt + 1 < NT)
            load_stage(sbase + ((kt + 1) & 1) * STAGE_BYTES, tid, gA, gB,
                       (kt + 1) * BK);
        CP_COMMIT();

        const uint32_t Ah = sbase + (kt & 1) * STAGE_BYTES;
        const uint32_t Al = Ah + TILE_BYTES;
        const uint32_t Bh = Al + TILE_BYTES;
        const uint32_t Bl = Bh + TILE_BYTES;

        #pragma unroll
        for (int ks = 0; ks < 2; ks++) {
            const int a_koff = (ks * 2 + a_chb) * 16;
            const int b_koff = (ks * 2 + b_ch) * 16;

            uint32_t af[4][4], bfh[2][4], bfl[2][4];
            #pragma unroll
            for (int bi = 0; bi < 2; bi++) {
                ldmatrix4(bfh[bi], Bh + (b_row + bi * 16) * ROW_STRIDE + b_koff);
                ldmatrix4(bfl[bi], Bl + (b_row + bi * 16) * ROW_STRIDE + b_koff);
            }
            #pragma unroll
            for (int mi = 0; mi < 4; mi++)
                ldmatrix4(af[mi], Ah + (a_row + mi * 16) * ROW_STRIDE + a_koff);

            // hi*hi and hi*lo
            #pragma unroll
            for (int mi = 0; mi < 4; mi++) {
                #pragma unroll
                for (int ni = 0; ni < 4; ni++) {
                    mma16816(acc[mi][ni], af[mi], &bfh[ni >> 1][(ni & 1) * 2]);
                    mma16816(acc[mi][ni], af[mi], &bfl[ni >> 1][(ni & 1) * 2]);
                }
            }
            // lo*hi (reuse af registers)
            #pragma unroll
            for (int mi = 0; mi < 4; mi++)
                ldmatrix4(af[mi], Al + (a_row + mi * 16) * ROW_STRIDE + a_koff);
            #pragma unroll
            for (int mi = 0; mi < 4; mi++) {
                #pragma unroll
                for (int ni = 0; ni < 4; ni++)
                    mma16816(acc[mi][ni], af[mi], &bfh[ni >> 1][(ni & 1) * 2]);
            }
        }
    }

    // Epilogue
    const int l4 = lane >> 2;
    const int l2 = (lane & 3) * 2;
    #pragma unroll
    for (int ni = 0; ni < 4; ni++) {
        const int col = n0 + warp_n * 32 + ni * 8 + l2;
        const float2 bv = *reinterpret_cast<const float2*>(&bias[col]);
        #pragma unroll
        for (int mi = 0; mi < 4; mi++) {
            const int row = m0 + warp_m * 64 + mi * 16 + l4;
            float2 v0, v1;
            v0.x = acc[mi][ni][0] + bv.x;
            v0.y = acc[mi][ni][1] + bv.y;
            v1.x = acc[mi][ni][2] + bv.x;
            v1.y = acc[mi][ni][3] + bv.y;
            *reinterpret_cast<float2*>(&C[(size_t)row * N + col]) = v0;
            *reinterpret_cast<float2*>(&C[(size_t)(row + 8) * N + col]) = v1;
        }
    }
}

// ---------------- launch ----------------

extern "C" void kernel_launch(void* const* d_in, const int* in_sizes, int n_in,
                              void* d_out, int out_size) {
    const float* x    = (const float*)d_in[0];
    const float* w    = (const float*)d_in[1];
    const float* bias = (const float*)d_in[2];
    const float* sw   = (const float*)d_in[3];
    const int*   idx  = (const int*)d_in[4];
    float* out = (float*)d_out;

    const int N = in_sizes[2];        // 4096
    const int K = in_sizes[1] / N;    // 4096
    const int M = in_sizes[0] / K;    // 8192
    const int nnz = in_sizes[3];      // 262144

    static bool attr_done = false;
    if (!attr_done) {
        cudaFuncSetAttribute(gemm_kernel,
                             cudaFuncAttributeMaxDynamicSharedMemorySize, SMEM_TOTAL);
        attr_done = true;
    }

    prep_wcopy_kernel<<<1024, 256>>>(w, (N * K) / 4);
    prep_scatter_kernel<<<(nnz + 255) / 256, 256>>>(sw, idx, idx + nnz, nnz, K);
    prep_wsplit_kernel<<<1024, 256>>>((N * K) / 4, K);
    prep_xsplit_kernel<<<2048, 256>>>(x, (M / 4) * K, K);

    dim3 grid(N / BN, M / BM);   // (32, 64)
    gemm_kernel<<<grid, 256, SMEM_TOTAL>>>(bias, out, N);
}

// round 6
// speedup vs baseline: 1.5255x; 1.1805x over previous
#include <cuda_runtime.h>
#include <cuda_bf16.h>
#include <cstdint>

// ----------------------------------------------------------------------------
// Round 6: bf16x3 GEMM, fragment-level reuse, XOR-swizzled smem (no pad),
// 3-stage cp.async pipeline (wait_group 1 instead of full drain).
//   A = [hi(x)|lo(x)]  [8192, 8192] bf16    B = [hi(W)|lo(W)]  [4096, 8192]
//   per chunk: acc += Ahi*Bhi + Ahi*Blo + Alo*Bhi   (fp32 accum)
// CTA 128x128 (2 CTAs/SM), warp tile 64x32, BK=32.
// ----------------------------------------------------------------------------

#define BM 128
#define BN 128
#define BK 32
#define STAGES 3
#define K2 8192
#define TILE_BYTES (128 * 64)                 // 8192 (64B rows, swizzled)
#define STAGE_BYTES (4 * TILE_BYTES)          // Ahi,Alo,Bhi,Blo = 32768
#define SMEM_TOTAL (STAGES * STAGE_BYTES)     // 98304

__device__ float          g_Wf[4096u * 4096u];          // 64 MB
__device__ __nv_bfloat16  g_A[8192u * 8192u];           // 128 MB
__device__ __nv_bfloat16  g_B[4096u * 8192u];           // 64 MB

// ---------------- helpers ----------------

__device__ __forceinline__ uint32_t smem_u32(const void* p) {
    uint32_t a;
    asm("{ .reg .u64 t; cvta.to.shared.u64 t, %1; cvt.u32.u64 %0, t; }"
        : "=r"(a) : "l"(p));
    return a;
}

// Swizzled byte offset of 16B chunk (row, ch): conflict-free for 8-row
// ldmatrix groups and for cp.async writes.
__device__ __forceinline__ uint32_t swz(int row, int ch) {
    return (uint32_t)(row * 64 + ((ch ^ ((row >> 1) & 3)) << 4));
}

__device__ __forceinline__ void cp_async16(uint32_t dst, const void* src) {
    asm volatile("cp.async.cg.shared.global [%0], [%1], 16;"
                 :: "r"(dst), "l"(src) : "memory");
}
#define CP_COMMIT() asm volatile("cp.async.commit_group;" ::: "memory")
#define CP_WAIT(n)  asm volatile("cp.async.wait_group %0;" :: "n"(n) : "memory")

__device__ __forceinline__ void ldmatrix4(uint32_t* r, uint32_t addr) {
    asm volatile("ldmatrix.sync.aligned.m8n8.x4.shared.b16 {%0,%1,%2,%3}, [%4];"
                 : "=r"(r[0]), "=r"(r[1]), "=r"(r[2]), "=r"(r[3]) : "r"(addr));
}

__device__ __forceinline__ void mma16816(float* d, const uint32_t* a,
                                         const uint32_t* b) {
    asm volatile(
        "mma.sync.aligned.m16n8k16.row.col.f32.bf16.bf16.f32 "
        "{%0,%1,%2,%3}, {%4,%5,%6,%7}, {%8,%9}, {%0,%1,%2,%3};"
        : "+f"(d[0]), "+f"(d[1]), "+f"(d[2]), "+f"(d[3])
        : "r"(a[0]), "r"(a[1]), "r"(a[2]), "r"(a[3]), "r"(b[0]), "r"(b[1]));
}

// ---------------- Phase 1 ----------------

__global__ void prep_wcopy_kernel(const float* __restrict__ w, int n4) {
    float4* dst = reinterpret_cast<float4*>(g_Wf);
    const float4* src = reinterpret_cast<const float4*>(w);
    for (int i = blockIdx.x * blockDim.x + threadIdx.x; i < n4;
         i += gridDim.x * blockDim.x)
        dst[i] = src[i];
}

__global__ void prep_scatter_kernel(const float* __restrict__ sw,
                                    const int* __restrict__ rows,
                                    const int* __restrict__ cols,
                                    int nnz, int K) {
    int i = blockIdx.x * blockDim.x + threadIdx.x;
    if (i < nnz)
        atomicAdd(&g_Wf[(size_t)rows[i] * K + cols[i]], sw[i]);
}

__device__ __forceinline__ void split2(float x, float y,
                                       __nv_bfloat162& hi, __nv_bfloat162& lo) {
    __nv_bfloat16 hx = __float2bfloat16_rn(x);
    __nv_bfloat16 hy = __float2bfloat16_rn(y);
    __nv_bfloat16 lx = __float2bfloat16_rn(x - __bfloat162float(hx));
    __nv_bfloat16 ly = __float2bfloat16_rn(y - __bfloat162float(hy));
    hi = __nv_bfloat162(hx, hy);
    lo = __nv_bfloat162(lx, ly);
}

__global__ void prep_wsplit_kernel(int n4, int K) {
    const float4* src = reinterpret_cast<const float4*>(g_Wf);
    const int rowq = K / 4;
    for (int i = blockIdx.x * blockDim.x + threadIdx.x; i < n4;
         i += gridDim.x * blockDim.x) {
        float4 v = src[i];
        int row = i / rowq, col = (i % rowq) * 4;
        __nv_bfloat162 h0, l0, h1, l1;
        split2(v.x, v.y, h0, l0);
        split2(v.z, v.w, h1, l1);
        size_t base = (size_t)row * K2 + col;
        __nv_bfloat162* ph = reinterpret_cast<__nv_bfloat162*>(&g_B[base]);
        __nv_bfloat162* pl = reinterpret_cast<__nv_bfloat162*>(&g_B[base + K]);
        ph[0] = h0; ph[1] = h1;
        pl[0] = l0; pl[1] = l1;
    }
}

__global__ void prep_xsplit_kernel(const float* __restrict__ x, int n4, int K) {
    const float4* src = reinterpret_cast<const float4*>(x);
    const int rowq = K / 4;
    for (int i = blockIdx.x * blockDim.x + threadIdx.x; i < n4;
         i += gridDim.x * blockDim.x) {
        float4 v = src[i];
        int row = i / rowq, col = (i % rowq) * 4;
        __nv_bfloat162 h0, l0, h1, l1;
        split2(v.x, v.y, h0, l0);
        split2(v.z, v.w, h1, l1);
        size_t base = (size_t)row * K2 + col;
        __nv_bfloat162* ph = reinterpret_cast<__nv_bfloat162*>(&g_A[base]);
        __nv_bfloat162* pl = reinterpret_cast<__nv_bfloat162*>(&g_A[base + K]);
        ph[0] = h0; ph[1] = h1;
        pl[0] = l0; pl[1] = l1;
    }
}

// ---------------- Phase 2: GEMM ----------------
// Stage layout: [Ahi | Alo | Bhi | Blo], each 128 rows x 64B swizzled.

__device__ __forceinline__ void load_stage(uint32_t stage_base, int tid,
                                           const __nv_bfloat16* gA,
                                           const __nv_bfloat16* gB, int k0) {
    #pragma unroll
    for (int t = 0; t < 4; t++) {
        const __nv_bfloat16* src_base = (t < 2) ? gA : gB;
        const int kofs = k0 + (t & 1) * 4096;    // hi at k0, lo at k0+4096
        const uint32_t dbase = stage_base + t * TILE_BYTES;
        #pragma unroll
        for (int i = 0; i < 2; i++) {
            int u = i * 256 + tid;
            int row = u >> 2, ch = u & 3;
            cp_async16(dbase + swz(row, ch),
                       src_base + (size_t)row * K2 + kofs + ch * 8);
        }
    }
}

__global__ __launch_bounds__(256, 2)
void gemm_kernel(const float* __restrict__ bias, float* __restrict__ C, int N) {
    extern __shared__ char smem[];
    const uint32_t sbase = smem_u32(smem);

    const int tid = threadIdx.x;
    const int warp = tid >> 5;
    const int lane = tid & 31;
    const int warp_m = warp & 1;     // 2 (m) x 4 (n), warp tile 64x32
    const int warp_n = warp >> 1;

    const int m0 = blockIdx.y * BM;
    const int n0 = blockIdx.x * BN;

    const __nv_bfloat16* gA = g_A + (size_t)m0 * K2;
    const __nv_bfloat16* gB = g_B + (size_t)n0 * K2;

    const int a_row = warp_m * 64 + (lane & 15);
    const int a_chb = lane >> 4;
    const int b_row = warp_n * 32 + ((lane >> 4) << 3) + (lane & 7);
    const int b_ch  = (lane >> 3) & 1;

    float acc[4][4][4] = {};   // 64 regs

    // Prologue: stages 0,1
    load_stage(sbase, tid, gA, gB, 0);
    CP_COMMIT();
    load_stage(sbase + STAGE_BYTES, tid, gA, gB, BK);
    CP_COMMIT();

    const int NT = 4096 / BK;   // 128 chunks
    int s_cur = 0;              // stage of chunk kt
    for (int kt = 0; kt < NT; kt++) {
        CP_WAIT(1);             // stage kt ready; kt+1 may still fly
        __syncthreads();

        const int pf = kt + 2;
        if (pf < NT) {
            int s_nxt = s_cur + 2;
            if (s_nxt >= STAGES) s_nxt -= STAGES;
            load_stage(sbase + s_nxt * STAGE_BYTES, tid, gA, gB, pf * BK);
        }
        CP_COMMIT();

        const uint32_t Ah = sbase + s_cur * STAGE_BYTES;
        const uint32_t Al = Ah + TILE_BYTES;
        const uint32_t Bh = Al + TILE_BYTES;
        const uint32_t Bl = Bh + TILE_BYTES;

        #pragma unroll
        for (int ks = 0; ks < 2; ks++) {
            uint32_t af[4][4], bfh[2][4], bfl[2][4];
            #pragma unroll
            for (int bi = 0; bi < 2; bi++) {
                const int br = b_row + bi * 16;
                ldmatrix4(bfh[bi], Bh + swz(br, ks * 2 + b_ch));
                ldmatrix4(bfl[bi], Bl + swz(br, ks * 2 + b_ch));
            }
            #pragma unroll
            for (int mi = 0; mi < 4; mi++)
                ldmatrix4(af[mi], Ah + swz(a_row + mi * 16, ks * 2 + a_chb));

            // hi*hi and hi*lo
            #pragma unroll
            for (int mi = 0; mi < 4; mi++) {
                #pragma unroll
                for (int ni = 0; ni < 4; ni++) {
                    mma16816(acc[mi][ni], af[mi], &bfh[ni >> 1][(ni & 1) * 2]);
                    mma16816(acc[mi][ni], af[mi], &bfl[ni >> 1][(ni & 1) * 2]);
                }
            }
            // lo*hi (reuse af registers)
            #pragma unroll
            for (int mi = 0; mi < 4; mi++)
                ldmatrix4(af[mi], Al + swz(a_row + mi * 16, ks * 2 + a_chb));
            #pragma unroll
            for (int mi = 0; mi < 4; mi++) {
                #pragma unroll
                for (int ni = 0; ni < 4; ni++)
                    mma16816(acc[mi][ni], af[mi], &bfh[ni >> 1][(ni & 1) * 2]);
            }
        }

        if (++s_cur == STAGES) s_cur = 0;
    }

    // Epilogue
    const int l4 = lane >> 2;
    const int l2 = (lane & 3) * 2;
    #pragma unroll
    for (int ni = 0; ni < 4; ni++) {
        const int col = n0 + warp_n * 32 + ni * 8 + l2;
        const float2 bv = *reinterpret_cast<const float2*>(&bias[col]);
        #pragma unroll
        for (int mi = 0; mi < 4; mi++) {
            const int row = m0 + warp_m * 64 + mi * 16 + l4;
            float2 v0, v1;
            v0.x = acc[mi][ni][0] + bv.x;
            v0.y = acc[mi][ni][1] + bv.y;
            v1.x = acc[mi][ni][2] + bv.x;
            v1.y = acc[mi][ni][3] + bv.y;
            *reinterpret_cast<float2*>(&C[(size_t)row * N + col]) = v0;
            *reinterpret_cast<float2*>(&C[(size_t)(row + 8) * N + col]) = v1;
        }
    }
}

// ---------------- launch ----------------

extern "C" void kernel_launch(void* const* d_in, const int* in_sizes, int n_in,
                              void* d_out, int out_size) {
    const float* x    = (const float*)d_in[0];
    const float* w    = (const float*)d_in[1];
    const float* bias = (const float*)d_in[2];
    const float* sw   = (const float*)d_in[3];
    const int*   idx  = (const int*)d_in[4];
    float* out = (float*)d_out;

    const int N = in_sizes[2];        // 4096
    const int K = in_sizes[1] / N;    // 4096
    const int M = in_sizes[0] / K;    // 8192
    const int nnz = in_sizes[3];      // 262144

    static bool attr_done = false;
    if (!attr_done) {
        cudaFuncSetAttribute(gemm_kernel,
                             cudaFuncAttributeMaxDynamicSharedMemorySize, SMEM_TOTAL);
        attr_done = true;
    }

    prep_wcopy_kernel<<<1024, 256>>>(w, (N * K) / 4);
    prep_scatter_kernel<<<(nnz + 255) / 256, 256>>>(sw, idx, idx + nnz, nnz, K);
    prep_wsplit_kernel<<<1024, 256>>>((N * K) / 4, K);
    prep_xsplit_kernel<<<2048, 256>>>(x, (M / 4) * K, K);

    dim3 grid(N / BN, M / BM);   // (32, 64)
    gemm_kernel<<<grid, 256, SMEM_TOTAL>>>(bias, out, N);
}

// round 7
// speedup vs baseline: 2.1531x; 1.4114x over previous
#include <cuda_runtime.h>
#include <cuda_fp16.h>
#include <cstdint>

// ----------------------------------------------------------------------------
// Round 7: fp16 2-product GEMM.
//   Wf = W + scatter(delta)  (fp32)
//   A  = fp16(x)                       [8192, 4096]
//   B  = [fp16hi(Wf) | fp16lo(Wf)]     [4096, 8192]
//   out = A*Bhi + A*Blo + bias  (fp32 accum); dropped term l(x)*W ~ 1.6e-4.
// CTA 128x128 (2 CTAs/SM), warp tile 64x32, BK=32, 4-stage cp.async pipeline,
// XOR-swizzled smem.
// ----------------------------------------------------------------------------

#define BM 128
#define BN 128
#define BK 32
#define STAGES 4
#define KA 4096
#define KB 8192
#define TILE_BYTES (128 * 64)                 // 8192
#define STAGE_BYTES (3 * TILE_BYTES)          // Ah,Bh,Bl = 24576
#define SMEM_TOTAL (STAGES * STAGE_BYTES)     // 98304

__device__ float   g_Wf[4096u * 4096u];       // 64 MB
__device__ __half  g_A[8192u * 4096u];        // 64 MB
__device__ __half  g_B[4096u * 8192u];        // 64 MB

// ---------------- helpers ----------------

__device__ __forceinline__ uint32_t smem_u32(const void* p) {
    uint32_t a;
    asm("{ .reg .u64 t; cvta.to.shared.u64 t, %1; cvt.u32.u64 %0, t; }"
        : "=r"(a) : "l"(p));
    return a;
}

// Swizzled byte offset of 16B chunk (row, ch); conflict-free for cp.async
// writes and 8-row ldmatrix reads (validated in round 6).
__device__ __forceinline__ uint32_t swz(int row, int ch) {
    return (uint32_t)(row * 64 + ((ch ^ ((row >> 1) & 3)) << 4));
}

__device__ __forceinline__ void cp_async16(uint32_t dst, const void* src) {
    asm volatile("cp.async.cg.shared.global [%0], [%1], 16;"
                 :: "r"(dst), "l"(src) : "memory");
}
#define CP_COMMIT() asm volatile("cp.async.commit_group;" ::: "memory")
#define CP_WAIT(n)  asm volatile("cp.async.wait_group %0;" :: "n"(n) : "memory")

__device__ __forceinline__ void ldmatrix4(uint32_t* r, uint32_t addr) {
    asm volatile("ldmatrix.sync.aligned.m8n8.x4.shared.b16 {%0,%1,%2,%3}, [%4];"
                 : "=r"(r[0]), "=r"(r[1]), "=r"(r[2]), "=r"(r[3]) : "r"(addr));
}

__device__ __forceinline__ void mma16816(float* d, const uint32_t* a,
                                         const uint32_t* b) {
    asm volatile(
        "mma.sync.aligned.m16n8k16.row.col.f32.f16.f16.f32 "
        "{%0,%1,%2,%3}, {%4,%5,%6,%7}, {%8,%9}, {%0,%1,%2,%3};"
        : "+f"(d[0]), "+f"(d[1]), "+f"(d[2]), "+f"(d[3])
        : "r"(a[0]), "r"(a[1]), "r"(a[2]), "r"(a[3]), "r"(b[0]), "r"(b[1]));
}

// ---------------- Phase 1 ----------------

__global__ void prep_wcopy_kernel(const float* __restrict__ w, int n4) {
    float4* dst = reinterpret_cast<float4*>(g_Wf);
    const float4* src = reinterpret_cast<const float4*>(w);
    for (int i = blockIdx.x * blockDim.x + threadIdx.x; i < n4;
         i += gridDim.x * blockDim.x)
        dst[i] = src[i];
}

__global__ void prep_scatter_kernel(const float* __restrict__ sw,
                                    const int* __restrict__ rows,
                                    const int* __restrict__ cols,
                                    int nnz, int K) {
    int i = blockIdx.x * blockDim.x + threadIdx.x;
    if (i < nnz)
        atomicAdd(&g_Wf[(size_t)rows[i] * K + cols[i]], sw[i]);
}

// B row n: [ fp16hi(Wf) (4096) | fp16lo(Wf) (4096) ]
__global__ void prep_wsplit_kernel(int n4, int K) {
    const float4* src = reinterpret_cast<const float4*>(g_Wf);
    const int rowq = K / 4;
    for (int i = blockIdx.x * blockDim.x + threadIdx.x; i < n4;
         i += gridDim.x * blockDim.x) {
        float4 v = src[i];
        int row = i / rowq, col = (i % rowq) * 4;
        __half hx = __float2half_rn(v.x), hy = __float2half_rn(v.y);
        __half hz = __float2half_rn(v.z), hw = __float2half_rn(v.w);
        __half lx = __float2half_rn(v.x - __half2float(hx));
        __half ly = __float2half_rn(v.y - __half2float(hy));
        __half lz = __float2half_rn(v.z - __half2float(hz));
        __half lw = __float2half_rn(v.w - __half2float(hw));
        size_t base = (size_t)row * KB + col;
        __half2* ph = reinterpret_cast<__half2*>(&g_B[base]);
        __half2* pl = reinterpret_cast<__half2*>(&g_B[base + K]);
        ph[0] = __halves2half2(hx, hy);
        ph[1] = __halves2half2(hz, hw);
        pl[0] = __halves2half2(lx, ly);
        pl[1] = __halves2half2(lz, lw);
    }
}

// A: plain fp16 convert of x
__global__ void prep_xh_kernel(const float* __restrict__ x, int n4) {
    const float4* src = reinterpret_cast<const float4*>(x);
    __half2* dst = reinterpret_cast<__half2*>(g_A);
    for (int i = blockIdx.x * blockDim.x + threadIdx.x; i < n4;
         i += gridDim.x * blockDim.x) {
        float4 v = src[i];
        dst[i * 2]     = __halves2half2(__float2half_rn(v.x), __float2half_rn(v.y));
        dst[i * 2 + 1] = __halves2half2(__float2half_rn(v.z), __float2half_rn(v.w));
    }
}

// ---------------- Phase 2: GEMM ----------------
// Stage layout: [Ah | Bh | Bl], each 128 rows x 64B swizzled.

__device__ __forceinline__ void load_stage(uint32_t stage_base, int tid,
                                           const __half* gA,
                                           const __half* gB, int k0) {
    // Ah tile
    {
        const uint32_t dbase = stage_base;
        #pragma unroll
        for (int i = 0; i < 2; i++) {
            int u = i * 256 + tid;
            int row = u >> 2, ch = u & 3;
            cp_async16(dbase + swz(row, ch),
                       gA + (size_t)row * KA + k0 + ch * 8);
        }
    }
    // Bh, Bl tiles
    #pragma unroll
    for (int t = 0; t < 2; t++) {
        const int kofs = k0 + t * 4096;
        const uint32_t dbase = stage_base + (1 + t) * TILE_BYTES;
        #pragma unroll
        for (int i = 0; i < 2; i++) {
            int u = i * 256 + tid;
            int row = u >> 2, ch = u & 3;
            cp_async16(dbase + swz(row, ch),
                       gB + (size_t)row * KB + kofs + ch * 8);
        }
    }
}

__global__ __launch_bounds__(256, 2)
void gemm_kernel(const float* __restrict__ bias, float* __restrict__ C, int N) {
    extern __shared__ char smem[];
    const uint32_t sbase = smem_u32(smem);

    const int tid = threadIdx.x;
    const int warp = tid >> 5;
    const int lane = tid & 31;
    const int warp_m = warp & 1;     // 2 (m) x 4 (n), warp tile 64x32
    const int warp_n = warp >> 1;

    const int m0 = blockIdx.y * BM;
    const int n0 = blockIdx.x * BN;

    const __half* gA = g_A + (size_t)m0 * KA;
    const __half* gB = g_B + (size_t)n0 * KB;

    const int a_row = warp_m * 64 + (lane & 15);
    const int a_chb = lane >> 4;
    const int b_row = warp_n * 32 + ((lane >> 4) << 3) + (lane & 7);
    const int b_ch  = (lane >> 3) & 1;

    float acc[4][4][4] = {};   // 64 regs

    // Prologue: stages 0..2
    #pragma unroll
    for (int s = 0; s < STAGES - 1; s++) {
        load_stage(sbase + s * STAGE_BYTES, tid, gA, gB, s * BK);
        CP_COMMIT();
    }

    const int NT = 4096 / BK;   // 128 chunks
    int s_cur = 0;
    for (int kt = 0; kt < NT; kt++) {
        CP_WAIT(2);             // stage kt ready; kt+1, kt+2 may still fly
        __syncthreads();

        const int pf = kt + STAGES - 1;
        if (pf < NT) {
            int s_nxt = s_cur + STAGES - 1;
            if (s_nxt >= STAGES) s_nxt -= STAGES;
            load_stage(sbase + s_nxt * STAGE_BYTES, tid, gA, gB, pf * BK);
        }
        CP_COMMIT();

        const uint32_t Ah = sbase + s_cur * STAGE_BYTES;
        const uint32_t Bh = Ah + TILE_BYTES;
        const uint32_t Bl = Bh + TILE_BYTES;

        #pragma unroll
        for (int ks = 0; ks < 2; ks++) {
            uint32_t af[4][4], bfh[2][4], bfl[2][4];
            #pragma unroll
            for (int bi = 0; bi < 2; bi++) {
                const int br = b_row + bi * 16;
                ldmatrix4(bfh[bi], Bh + swz(br, ks * 2 + b_ch));
                ldmatrix4(bfl[bi], Bl + swz(br, ks * 2 + b_ch));
            }
            #pragma unroll
            for (int mi = 0; mi < 4; mi++)
                ldmatrix4(af[mi], Ah + swz(a_row + mi * 16, ks * 2 + a_chb));

            #pragma unroll
            for (int mi = 0; mi < 4; mi++) {
                #pragma unroll
                for (int ni = 0; ni < 4; ni++) {
                    mma16816(acc[mi][ni], af[mi], &bfh[ni >> 1][(ni & 1) * 2]);
                    mma16816(acc[mi][ni], af[mi], &bfl[ni >> 1][(ni & 1) * 2]);
                }
            }
        }

        if (++s_cur == STAGES) s_cur = 0;
    }

    // Epilogue
    const int l4 = lane >> 2;
    const int l2 = (lane & 3) * 2;
    #pragma unroll
    for (int ni = 0; ni < 4; ni++) {
        const int col = n0 + warp_n * 32 + ni * 8 + l2;
        const float2 bv = *reinterpret_cast<const float2*>(&bias[col]);
        #pragma unroll
        for (int mi = 0; mi < 4; mi++) {
            const int row = m0 + warp_m * 64 + mi * 16 + l4;
            float2 v0, v1;
            v0.x = acc[mi][ni][0] + bv.x;
            v0.y = acc[mi][ni][1] + bv.y;
            v1.x = acc[mi][ni][2] + bv.x;
            v1.y = acc[mi][ni][3] + bv.y;
            *reinterpret_cast<float2*>(&C[(size_t)row * N + col]) = v0;
            *reinterpret_cast<float2*>(&C[(size_t)(row + 8) * N + col]) = v1;
        }
    }
}

// ---------------- launch ----------------

extern "C" void kernel_launch(void* const* d_in, const int* in_sizes, int n_in,
                              void* d_out, int out_size) {
    const float* x    = (const float*)d_in[0];
    const float* w    = (const float*)d_in[1];
    const float* bias = (const float*)d_in[2];
    const float* sw   = (const float*)d_in[3];
    const int*   idx  = (const int*)d_in[4];
    float* out = (float*)d_out;

    const int N = in_sizes[2];        // 4096
    const int K = in_sizes[1] / N;    // 4096
    const int M = in_sizes[0] / K;    // 8192
    const int nnz = in_sizes[3];      // 262144

    static bool attr_done = false;
    if (!attr_done) {
        cudaFuncSetAttribute(gemm_kernel,
                             cudaFuncAttributeMaxDynamicSharedMemorySize, SMEM_TOTAL);
        attr_done = true;
    }

    prep_wcopy_kernel<<<1024, 256>>>(w, (N * K) / 4);
    prep_scatter_kernel<<<(nnz + 255) / 256, 256>>>(sw, idx, idx + nnz, nnz, K);
    prep_wsplit_kernel<<<1024, 256>>>((N * K) / 4, K);
    prep_xh_kernel<<<2048, 256>>>(x, (M / 4) * K);

    dim3 grid(N / BN, M / BM);   // (32, 64)
    gemm_kernel<<<grid, 256, SMEM_TOTAL>>>(bias, out, N);
}

// round 8
// speedup vs baseline: 3.9065x; 1.8144x over previous
#include <cuda_runtime.h>
#include <cuda_fp16.h>
#include <cstdint>

// ----------------------------------------------------------------------------
// Round 8: single-product fp16 GEMM.
//   Wf = W + scatter(delta)  (fp32)
//   A  = fp16(x)    [8192, 4096]      B = fp16(Wf)   [4096, 4096]
//   out = A @ B^T + bias  (fp32 accum)
//   Dropped terms x_lo*W (+2.1e-4) and x*W_lo (+~2.1e-4, independent)
//   => predicted rel_err ~2.9e-4 vs 1e-3 gate.
// CTA 128x128 (2 CTAs/SM), warp tile 64x32, BK=32, 5-stage cp.async pipeline,
// XOR-swizzled smem. A+B (96 MB fp16) fit in L2 -> compute-bound.
// ----------------------------------------------------------------------------

#define BM 128
#define BN 128
#define BK 32
#define STAGES 5
#define KK 4096
#define TILE_BYTES (128 * 64)                 // 8192
#define STAGE_BYTES (2 * TILE_BYTES)          // Ah,Bh = 16384
#define SMEM_TOTAL (STAGES * STAGE_BYTES)     // 81920

__device__ float   g_Wf[4096u * 4096u];       // 64 MB
__device__ __half  g_A[8192u * 4096u];        // 64 MB
__device__ __half  g_B[4096u * 4096u];        // 32 MB

// ---------------- helpers ----------------

__device__ __forceinline__ uint32_t smem_u32(const void* p) {
    uint32_t a;
    asm("{ .reg .u64 t; cvta.to.shared.u64 t, %1; cvt.u32.u64 %0, t; }"
        : "=r"(a) : "l"(p));
    return a;
}

// Swizzled byte offset of 16B chunk (row, ch); conflict-free for cp.async
// writes and 8-row ldmatrix reads (validated rounds 6-7).
__device__ __forceinline__ uint32_t swz(int row, int ch) {
    return (uint32_t)(row * 64 + ((ch ^ ((row >> 1) & 3)) << 4));
}

__device__ __forceinline__ void cp_async16(uint32_t dst, const void* src) {
    asm volatile("cp.async.cg.shared.global [%0], [%1], 16;"
                 :: "r"(dst), "l"(src) : "memory");
}
#define CP_COMMIT() asm volatile("cp.async.commit_group;" ::: "memory")
#define CP_WAIT(n)  asm volatile("cp.async.wait_group %0;" :: "n"(n) : "memory")

__device__ __forceinline__ void ldmatrix4(uint32_t* r, uint32_t addr) {
    asm volatile("ldmatrix.sync.aligned.m8n8.x4.shared.b16 {%0,%1,%2,%3}, [%4];"
                 : "=r"(r[0]), "=r"(r[1]), "=r"(r[2]), "=r"(r[3]) : "r"(addr));
}

__device__ __forceinline__ void mma16816(float* d, const uint32_t* a,
                                         const uint32_t* b) {
    asm volatile(
        "mma.sync.aligned.m16n8k16.row.col.f32.f16.f16.f32 "
        "{%0,%1,%2,%3}, {%4,%5,%6,%7}, {%8,%9}, {%0,%1,%2,%3};"
        : "+f"(d[0]), "+f"(d[1]), "+f"(d[2]), "+f"(d[3])
        : "r"(a[0]), "r"(a[1]), "r"(a[2]), "r"(a[3]), "r"(b[0]), "r"(b[1]));
}

// ---------------- Phase 1 ----------------

__global__ void prep_wcopy_kernel(const float* __restrict__ w, int n4) {
    float4* dst = reinterpret_cast<float4*>(g_Wf);
    const float4* src = reinterpret_cast<const float4*>(w);
    for (int i = blockIdx.x * blockDim.x + threadIdx.x; i < n4;
         i += gridDim.x * blockDim.x)
        dst[i] = src[i];
}

__global__ void prep_scatter_kernel(const float* __restrict__ sw,
                                    const int* __restrict__ rows,
                                    const int* __restrict__ cols,
                                    int nnz, int K) {
    int i = blockIdx.x * blockDim.x + threadIdx.x;
    if (i < nnz)
        atomicAdd(&g_Wf[(size_t)rows[i] * K + cols[i]], sw[i]);
}

__global__ void prep_wconv_kernel(int n4) {
    const float4* src = reinterpret_cast<const float4*>(g_Wf);
    __half2* dst = reinterpret_cast<__half2*>(g_B);
    for (int i = blockIdx.x * blockDim.x + threadIdx.x; i < n4;
         i += gridDim.x * blockDim.x) {
        float4 v = src[i];
        dst[i * 2]     = __halves2half2(__float2half_rn(v.x), __float2half_rn(v.y));
        dst[i * 2 + 1] = __halves2half2(__float2half_rn(v.z), __float2half_rn(v.w));
    }
}

__global__ void prep_xh_kernel(const float* __restrict__ x, int n4) {
    const float4* src = reinterpret_cast<const float4*>(x);
    __half2* dst = reinterpret_cast<__half2*>(g_A);
    for (int i = blockIdx.x * blockDim.x + threadIdx.x; i < n4;
         i += gridDim.x * blockDim.x) {
        float4 v = src[i];
        dst[i * 2]     = __halves2half2(__float2half_rn(v.x), __float2half_rn(v.y));
        dst[i * 2 + 1] = __halves2half2(__float2half_rn(v.z), __float2half_rn(v.w));
    }
}

// ---------------- Phase 2: GEMM ----------------
// Stage layout: [Ah | Bh], each 128 rows x 64B swizzled.

__device__ __forceinline__ void load_stage(uint32_t stage_base, int tid,
                                           const __half* gA,
                                           const __half* gB, int k0) {
    #pragma unroll
    for (int t = 0; t < 2; t++) {
        const __half* src_base = t ? gB : gA;
        const uint32_t dbase = stage_base + t * TILE_BYTES;
        #pragma unroll
        for (int i = 0; i < 2; i++) {
            int u = i * 256 + tid;
            int row = u >> 2, ch = u & 3;
            cp_async16(dbase + swz(row, ch),
                       src_base + (size_t)row * KK + k0 + ch * 8);
        }
    }
}

__global__ __launch_bounds__(256, 2)
void gemm_kernel(const float* __restrict__ bias, float* __restrict__ C, int N) {
    extern __shared__ char smem[];
    const uint32_t sbase = smem_u32(smem);

    const int tid = threadIdx.x;
    const int warp = tid >> 5;
    const int lane = tid & 31;
    const int warp_m = warp & 1;     // 2 (m) x 4 (n), warp tile 64x32
    const int warp_n = warp >> 1;

    const int m0 = blockIdx.y * BM;
    const int n0 = blockIdx.x * BN;

    const __half* gA = g_A + (size_t)m0 * KK;
    const __half* gB = g_B + (size_t)n0 * KK;

    const int a_row = warp_m * 64 + (lane & 15);
    const int a_chb = lane >> 4;
    const int b_row = warp_n * 32 + ((lane >> 4) << 3) + (lane & 7);
    const int b_ch  = (lane >> 3) & 1;

    float acc[4][4][4] = {};   // 64 regs

    // Prologue: stages 0..STAGES-2
    #pragma unroll
    for (int s = 0; s < STAGES - 1; s++) {
        load_stage(sbase + s * STAGE_BYTES, tid, gA, gB, s * BK);
        CP_COMMIT();
    }

    const int NT = KK / BK;   // 128 chunks
    int s_cur = 0;
    for (int kt = 0; kt < NT; kt++) {
        CP_WAIT(3);           // STAGES-2: stage kt ready, 3 more may fly
        __syncthreads();

        const int pf = kt + STAGES - 1;
        if (pf < NT) {
            int s_nxt = s_cur + STAGES - 1;
            if (s_nxt >= STAGES) s_nxt -= STAGES;
            load_stage(sbase + s_nxt * STAGE_BYTES, tid, gA, gB, pf * BK);
        }
        CP_COMMIT();

        const uint32_t Ah = sbase + s_cur * STAGE_BYTES;
        const uint32_t Bh = Ah + TILE_BYTES;

        #pragma unroll
        for (int ks = 0; ks < 2; ks++) {
            uint32_t af[4][4], bf[2][4];
            #pragma unroll
            for (int bi = 0; bi < 2; bi++)
                ldmatrix4(bf[bi], Bh + swz(b_row + bi * 16, ks * 2 + b_ch));
            #pragma unroll
            for (int mi = 0; mi < 4; mi++)
                ldmatrix4(af[mi], Ah + swz(a_row + mi * 16, ks * 2 + a_chb));

            #pragma unroll
            for (int mi = 0; mi < 4; mi++) {
                #pragma unroll
                for (int ni = 0; ni < 4; ni++)
                    mma16816(acc[mi][ni], af[mi], &bf[ni >> 1][(ni & 1) * 2]);
            }
        }

        if (++s_cur == STAGES) s_cur = 0;
    }

    // Epilogue
    const int l4 = lane >> 2;
    const int l2 = (lane & 3) * 2;
    #pragma unroll
    for (int ni = 0; ni < 4; ni++) {
        const int col = n0 + warp_n * 32 + ni * 8 + l2;
        const float2 bv = *reinterpret_cast<const float2*>(&bias[col]);
        #pragma unroll
        for (int mi = 0; mi < 4; mi++) {
            const int row = m0 + warp_m * 64 + mi * 16 + l4;
            float2 v0, v1;
            v0.x = acc[mi][ni][0] + bv.x;
            v0.y = acc[mi][ni][1] + bv.y;
            v1.x = acc[mi][ni][2] + bv.x;
            v1.y = acc[mi][ni][3] + bv.y;
            *reinterpret_cast<float2*>(&C[(size_t)row * N + col]) = v0;
            *reinterpret_cast<float2*>(&C[(size_t)(row + 8) * N + col]) = v1;
        }
    }
}

// ---------------- launch ----------------

extern "C" void kernel_launch(void* const* d_in, const int* in_sizes, int n_in,
                              void* d_out, int out_size) {
    const float* x    = (const float*)d_in[0];
    const float* w    = (const float*)d_in[1];
    const float* bias = (const float*)d_in[2];
    const float* sw   = (const float*)d_in[3];
    const int*   idx  = (const int*)d_in[4];
    float* out = (float*)d_out;

    const int N = in_sizes[2];        // 4096
    const int K = in_sizes[1] / N;    // 4096
    const int M = in_sizes[0] / K;    // 8192
    const int nnz = in_sizes[3];      // 262144

    static bool attr_done = false;
    if (!attr_done) {
        cudaFuncSetAttribute(gemm_kernel,
                             cudaFuncAttributeMaxDynamicSharedMemorySize, SMEM_TOTAL);
        attr_done = true;
    }

    prep_wcopy_kernel<<<1024, 256>>>(w, (N * K) / 4);
    prep_scatter_kernel<<<(nnz + 255) / 256, 256>>>(sw, idx, idx + nnz, nnz, K);
    prep_wconv_kernel<<<1024, 256>>>((N * K) / 4);
    prep_xh_kernel<<<2048, 256>>>(x, (M / 4) * K);

    dim3 grid(N / BN, M / BM);   // (32, 64)
    gemm_kernel<<<grid, 256, SMEM_TOTAL>>>(bias, out, N);
}

// round 10
// speedup vs baseline: 4.2106x; 1.0778x over previous
#include <cuda_runtime.h>
#include <cuda_fp16.h>
#include <cstdint>

// ----------------------------------------------------------------------------
// Round 9: single-product fp16 GEMM, streamlined prep + BK=64 pipeline.
//   B = fp16(W); scatter deltas directly into B via half atomics.
//   A = fp16(x).   out = A @ B^T + bias (fp32 accum).
// CTA 128x128 (2 CTAs/SM), warp tile 64x32, BK=64, 3-stage cp.async pipeline,
// 128B-row swizzle (ch ^= row&7).
// ----------------------------------------------------------------------------

#define BM 128
#define BN 128
#define BK 64
#define STAGES 3
#define KK 4096
#define TILE_BYTES (128 * 128)                // 16384 (128B rows)
#define STAGE_BYTES (2 * TILE_BYTES)          // A,B = 32768
#define SMEM_TOTAL (STAGES * STAGE_BYTES)     // 98304

__device__ __half  g_A[8192u * 4096u];        // 64 MB
__device__ __half  g_B[4096u * 4096u];        // 32 MB

// ---------------- helpers ----------------

__device__ __forceinline__ uint32_t smem_u32(const void* p) {
    uint32_t a;
    asm("{ .reg .u64 t; cvta.to.shared.u64 t, %1; cvt.u32.u64 %0, t; }"
        : "=r"(a) : "l"(p));
    return a;
}

// 128B-row swizzle: 16B chunk c (0..7) in row -> c ^ (row & 7).
__device__ __forceinline__ uint32_t swz(int row, int ch) {
    return (uint32_t)(row * 128 + ((ch ^ (row & 7)) << 4));
}

__device__ __forceinline__ void cp_async16(uint32_t dst, const void* src) {
    asm volatile("cp.async.cg.shared.global [%0], [%1], 16;"
                 :: "r"(dst), "l"(src) : "memory");
}
#define CP_COMMIT() asm volatile("cp.async.commit_group;" ::: "memory")
#define CP_WAIT(n)  asm volatile("cp.async.wait_group %0;" :: "n"(n) : "memory")

__device__ __forceinline__ void ldmatrix4(uint32_t* r, uint32_t addr) {
    asm volatile("ldmatrix.sync.aligned.m8n8.x4.shared.b16 {%0,%1,%2,%3}, [%4];"
                 : "=r"(r[0]), "=r"(r[1]), "=r"(r[2]), "=r"(r[3]) : "r"(addr));
}

__device__ __forceinline__ void mma16816(float* d, const uint32_t* a,
                                         const uint32_t* b) {
    asm volatile(
        "mma.sync.aligned.m16n8k16.row.col.f32.f16.f16.f32 "
        "{%0,%1,%2,%3}, {%4,%5,%6,%7}, {%8,%9}, {%0,%1,%2,%3};"
        : "+f"(d[0]), "+f"(d[1]), "+f"(d[2]), "+f"(d[3])
        : "r"(a[0]), "r"(a[1]), "r"(a[2]), "r"(a[3]), "r"(b[0]), "r"(b[1]));
}

// ---------------- Phase 1 ----------------

__global__ void prep_wconv_kernel(const float* __restrict__ w, int n4) {
    const float4* src = reinterpret_cast<const float4*>(w);
    __half2* dst = reinterpret_cast<__half2*>(g_B);
    for (int i = blockIdx.x * blockDim.x + threadIdx.x; i < n4;
         i += gridDim.x * blockDim.x) {
        float4 v = src[i];
        dst[i * 2]     = __halves2half2(__float2half_rn(v.x), __float2half_rn(v.y));
        dst[i * 2 + 1] = __halves2half2(__float2half_rn(v.z), __float2half_rn(v.w));
    }
}

__global__ void prep_scatter_kernel(const float* __restrict__ sw,
                                    const int* __restrict__ rows,
                                    const int* __restrict__ cols,
                                    int nnz, int K) {
    int i = blockIdx.x * blockDim.x + threadIdx.x;
    if (i < nnz)
        atomicAdd(&g_B[(size_t)rows[i] * K + cols[i]], __float2half_rn(sw[i]));
}

__global__ void prep_xh_kernel(const float* __restrict__ x, int n4) {
    const float4* src = reinterpret_cast<const float4*>(x);
    __half2* dst = reinterpret_cast<__half2*>(g_A);
    for (int i = blockIdx.x * blockDim.x + threadIdx.x; i < n4;
         i += gridDim.x * blockDim.x) {
        float4 v = src[i];
        dst[i * 2]     = __halves2half2(__float2half_rn(v.x), __float2half_rn(v.y));
        dst[i * 2 + 1] = __halves2half2(__float2half_rn(v.z), __float2half_rn(v.w));
    }
}

// ---------------- Phase 2: GEMM ----------------
// Stage layout: [A | B], each 128 rows x 128B swizzled.

__device__ __forceinline__ void load_stage(uint32_t stage_base, int tid,
                                           const __half* gA,
                                           const __half* gB, int k0) {
    // Per tile: 128 rows x 8 chunks = 1024 cp.async; 256 threads -> 4 iters.
    #pragma unroll
    for (int t = 0; t < 2; t++) {
        const __half* src_base = t ? gB : gA;
        const uint32_t dbase = stage_base + t * TILE_BYTES;
        #pragma unroll
        for (int i = 0; i < 4; i++) {
            int u = i * 256 + tid;
            int row = u >> 3, ch = u & 7;
            cp_async16(dbase + swz(row, ch),
                       src_base + (size_t)row * KK + k0 + ch * 8);
        }
    }
}

__global__ __launch_bounds__(256, 2)
void gemm_kernel(const float* __restrict__ bias, float* __restrict__ C, int N) {
    extern __shared__ char smem[];
    const uint32_t sbase = smem_u32(smem);

    const int tid = threadIdx.x;
    const int warp = tid >> 5;
    const int lane = tid & 31;
    const int warp_m = warp & 1;     // 2 (m) x 4 (n), warp tile 64x32
    const int warp_n = warp >> 1;

    const int m0 = blockIdx.y * BM;
    const int n0 = blockIdx.x * BN;

    const __half* gA = g_A + (size_t)m0 * KK;
    const __half* gB = g_B + (size_t)n0 * KK;

    const int a_row = warp_m * 64 + (lane & 15);
    const int a_chb = lane >> 4;                               // k-half bit
    const int b_row = warp_n * 32 + ((lane >> 4) << 3) + (lane & 7);
    const int b_ch  = (lane >> 3) & 1;

    float acc[4][4][4] = {};   // 64 regs

    // Prologue: stages 0,1
    #pragma unroll
    for (int s = 0; s < STAGES - 1; s++) {
        load_stage(sbase + s * STAGE_BYTES, tid, gA, gB, s * BK);
        CP_COMMIT();
    }

    const int NT = KK / BK;   // 64 chunks
    int s_cur = 0;
    for (int kt = 0; kt < NT; kt++) {
        CP_WAIT(1);           // stage kt ready; kt+1 may still fly
        __syncthreads();

        const int pf = kt + STAGES - 1;
        if (pf < NT) {
            int s_nxt = s_cur + STAGES - 1;
            if (s_nxt >= STAGES) s_nxt -= STAGES;
            load_stage(sbase + s_nxt * STAGE_BYTES, tid, gA, gB, pf * BK);
        }
        CP_COMMIT();

        const uint32_t Ah = sbase + s_cur * STAGE_BYTES;
        const uint32_t Bh = Ah + TILE_BYTES;

        #pragma unroll
        for (int ks = 0; ks < 4; ks++) {     // 4 x k16 per chunk
            uint32_t af[4][4], bf[2][4];
            #pragma unroll
            for (int bi = 0; bi < 2; bi++)
                ldmatrix4(bf[bi], Bh + swz(b_row + bi * 16, ks * 2 + b_ch));
            #pragma unroll
            for (int mi = 0; mi < 4; mi++)
                ldmatrix4(af[mi], Ah + swz(a_row + mi * 16, ks * 2 + a_chb));

            #pragma unroll
            for (int mi = 0; mi < 4; mi++) {
                #pragma unroll
                for (int ni = 0; ni < 4; ni++)
                    mma16816(acc[mi][ni], af[mi], &bf[ni >> 1][(ni & 1) * 2]);
            }
        }

        if (++s_cur == STAGES) s_cur = 0;
    }

    // Epilogue
    const int l4 = lane >> 2;
    const int l2 = (lane & 3) * 2;
    #pragma unroll
    for (int ni = 0; ni < 4; ni++) {
        const int col = n0 + warp_n * 32 + ni * 8 + l2;
        const float2 bv = *reinterpret_cast<const float2*>(&bias[col]);
        #pragma unroll
        for (int mi = 0; mi < 4; mi++) {
            const int row = m0 + warp_m * 64 + mi * 16 + l4;
            float2 v0, v1;
            v0.x = acc[mi][ni][0] + bv.x;
            v0.y = acc[mi][ni][1] + bv.y;
            v1.x = acc[mi][ni][2] + bv.x;
            v1.y = acc[mi][ni][3] + bv.y;
            *reinterpret_cast<float2*>(&C[(size_t)row * N + col]) = v0;
            *reinterpret_cast<float2*>(&C[(size_t)(row + 8) * N + col]) = v1;
        }
    }
}

// ---------------- launch ----------------

extern "C" void kernel_launch(void* const* d_in, const int* in_sizes, int n_in,
                              void* d_out, int out_size) {
    const float* x    = (const float*)d_in[0];
    const float* w    = (const float*)d_in[1];
    const float* bias = (const float*)d_in[2];
    const float* sw   = (const float*)d_in[3];
    const int*   idx  = (const int*)d_in[4];
    float* out = (float*)d_out;

    const int N = in_sizes[2];        // 4096
    const int K = in_sizes[1] / N;    // 4096
    const int M = in_sizes[0] / K;    // 8192
    const int nnz = in_sizes[3];      // 262144

    static bool attr_done = false;
    if (!attr_done) {
        cudaFuncSetAttribute(gemm_kernel,
                             cudaFuncAttributeMaxDynamicSharedMemorySize, SMEM_TOTAL);
        attr_done = true;
    }

    prep_wconv_kernel<<<1024, 256>>>(w, (N * K) / 4);
    prep_scatter_kernel<<<(nnz + 255) / 256, 256>>>(sw, idx, idx + nnz, nnz, K);
    prep_xh_kernel<<<2048, 256>>>(x, (M / 4) * K);

    dim3 grid(N / BN, M / BM);   // (32, 64)
    gemm_kernel<<<grid, 256, SMEM_TOTAL>>>(bias, out, N);
}

// round 11
// speedup vs baseline: 4.5750x; 1.0865x over previous
#include <cuda_runtime.h>
#include <cuda_fp16.h>
#include <cstdint>

// ----------------------------------------------------------------------------
// Round 10: fp16 GEMM, warp tile 64x64 (4 warps/CTA) to cut smem duplication.
//   B = fp16(W) + scattered deltas (half atomics);  A = fp16(x)
//   out = A @ B^T + bias (fp32 accum)
// CTA 128x128, 128 threads (warp grid 2x2), BK=64, 3-stage cp.async pipeline,
// 128B-row swizzle. smem/k16 per CTA: 24KB -> 16KB => tensor-pipe-bound.
// ----------------------------------------------------------------------------

#define BM 128
#define BN 128
#define BK 64
#define STAGES 3
#define KK 4096
#define TILE_BYTES (128 * 128)                // 16384
#define STAGE_BYTES (2 * TILE_BYTES)          // 32768
#define SMEM_TOTAL (STAGES * STAGE_BYTES)     // 98304

__device__ __half  g_A[8192u * 4096u];        // 64 MB
__device__ __half  g_B[4096u * 4096u];        // 32 MB

// ---------------- helpers ----------------

__device__ __forceinline__ uint32_t smem_u32(const void* p) {
    uint32_t a;
    asm("{ .reg .u64 t; cvta.to.shared.u64 t, %1; cvt.u32.u64 %0, t; }"
        : "=r"(a) : "l"(p));
    return a;
}

// 128B-row swizzle: 16B chunk c (0..7) in row -> c ^ (row & 7).
__device__ __forceinline__ uint32_t swz(int row, int ch) {
    return (uint32_t)(row * 128 + ((ch ^ (row & 7)) << 4));
}

__device__ __forceinline__ void cp_async16(uint32_t dst, const void* src) {
    asm volatile("cp.async.cg.shared.global [%0], [%1], 16;"
                 :: "r"(dst), "l"(src) : "memory");
}
#define CP_COMMIT() asm volatile("cp.async.commit_group;" ::: "memory")
#define CP_WAIT(n)  asm volatile("cp.async.wait_group %0;" :: "n"(n) : "memory")

__device__ __forceinline__ void ldmatrix4(uint32_t* r, uint32_t addr) {
    asm volatile("ldmatrix.sync.aligned.m8n8.x4.shared.b16 {%0,%1,%2,%3}, [%4];"
                 : "=r"(r[0]), "=r"(r[1]), "=r"(r[2]), "=r"(r[3]) : "r"(addr));
}

__device__ __forceinline__ void mma16816(float* d, const uint32_t* a,
                                         const uint32_t* b) {
    asm volatile(
        "mma.sync.aligned.m16n8k16.row.col.f32.f16.f16.f32 "
        "{%0,%1,%2,%3}, {%4,%5,%6,%7}, {%8,%9}, {%0,%1,%2,%3};"
        : "+f"(d[0]), "+f"(d[1]), "+f"(d[2]), "+f"(d[3])
        : "r"(a[0]), "r"(a[1]), "r"(a[2]), "r"(a[3]), "r"(b[0]), "r"(b[1]));
}

// ---------------- Phase 1 ----------------

__global__ void prep_wconv_kernel(const float* __restrict__ w, int n4) {
    const float4* src = reinterpret_cast<const float4*>(w);
    __half2* dst = reinterpret_cast<__half2*>(g_B);
    for (int i = blockIdx.x * blockDim.x + threadIdx.x; i < n4;
         i += gridDim.x * blockDim.x) {
        float4 v = src[i];
        dst[i * 2]     = __halves2half2(__float2half_rn(v.x), __float2half_rn(v.y));
        dst[i * 2 + 1] = __halves2half2(__float2half_rn(v.z), __float2half_rn(v.w));
    }
}

__global__ void prep_scatter_kernel(const float* __restrict__ sw,
                                    const int* __restrict__ rows,
                                    const int* __restrict__ cols,
                                    int nnz, int K) {
    int i = blockIdx.x * blockDim.x + threadIdx.x;
    if (i < nnz)
        atomicAdd(&g_B[(size_t)rows[i] * K + cols[i]], __float2half_rn(sw[i]));
}

__global__ void prep_xh_kernel(const float* __restrict__ x, int n4) {
    const float4* src = reinterpret_cast<const float4*>(x);
    __half2* dst = reinterpret_cast<__half2*>(g_A);
    for (int i = blockIdx.x * blockDim.x + threadIdx.x; i < n4;
         i += gridDim.x * blockDim.x) {
        float4 v = src[i];
        dst[i * 2]     = __halves2half2(__float2half_rn(v.x), __float2half_rn(v.y));
        dst[i * 2 + 1] = __halves2half2(__float2half_rn(v.z), __float2half_rn(v.w));
    }
}

// ---------------- Phase 2: GEMM ----------------
// Stage layout: [A | B], each 128 rows x 128B swizzled.

__device__ __forceinline__ void load_stage(uint32_t stage_base, int tid,
                                           const __half* gA,
                                           const __half* gB, int k0) {
    // Per tile: 1024 16B chunks; 128 threads -> 8 iters per tile.
    #pragma unroll
    for (int t = 0; t < 2; t++) {
        const __half* src_base = t ? gB : gA;
        const uint32_t dbase = stage_base + t * TILE_BYTES;
        #pragma unroll
        for (int i = 0; i < 8; i++) {
            int u = i * 128 + tid;
            int row = u >> 3, ch = u & 7;
            cp_async16(dbase + swz(row, ch),
                       src_base + (size_t)row * KK + k0 + ch * 8);
        }
    }
}

__global__ __launch_bounds__(128, 2)
void gemm_kernel(const float* __restrict__ bias, float* __restrict__ C, int N) {
    extern __shared__ char smem[];
    const uint32_t sbase = smem_u32(smem);

    const int tid = threadIdx.x;
    const int warp = tid >> 5;
    const int lane = tid & 31;
    const int warp_m = warp & 1;     // 2 (m) x 2 (n), warp tile 64x64
    const int warp_n = warp >> 1;

    const int m0 = blockIdx.y * BM;
    const int n0 = blockIdx.x * BN;

    const __half* gA = g_A + (size_t)m0 * KK;
    const __half* gB = g_B + (size_t)n0 * KK;

    const int a_row = warp_m * 64 + (lane & 15);
    const int a_chb = lane >> 4;                               // k-half bit
    const int b_row = warp_n * 64 + ((lane >> 4) << 3) + (lane & 7);
    const int b_ch  = (lane >> 3) & 1;

    float acc[4][8][4] = {};   // 128 regs: mi(4 x 16 rows) x ni(8 x 8 cols)

    // Prologue: stages 0,1
    #pragma unroll
    for (int s = 0; s < STAGES - 1; s++) {
        load_stage(sbase + s * STAGE_BYTES, tid, gA, gB, s * BK);
        CP_COMMIT();
    }

    const int NT = KK / BK;   // 64 chunks
    int s_cur = 0;
    for (int kt = 0; kt < NT; kt++) {
        CP_WAIT(1);           // stage kt ready; kt+1 may still fly
        __syncthreads();

        const int pf = kt + STAGES - 1;
        if (pf < NT) {
            int s_nxt = s_cur + STAGES - 1;
            if (s_nxt >= STAGES) s_nxt -= STAGES;
            load_stage(sbase + s_nxt * STAGE_BYTES, tid, gA, gB, pf * BK);
        }
        CP_COMMIT();

        const uint32_t Ah = sbase + s_cur * STAGE_BYTES;
        const uint32_t Bh = Ah + TILE_BYTES;

        #pragma unroll
        for (int ks = 0; ks < 4; ks++) {     // 4 x k16 per chunk
            uint32_t af[4][4], bf[4][4];
            #pragma unroll
            for (int bi = 0; bi < 4; bi++)
                ldmatrix4(bf[bi], Bh + swz(b_row + bi * 16, ks * 2 + b_ch));
            #pragma unroll
            for (int mi = 0; mi < 4; mi++)
                ldmatrix4(af[mi], Ah + swz(a_row + mi * 16, ks * 2 + a_chb));

            #pragma unroll
            for (int mi = 0; mi < 4; mi++) {
                #pragma unroll
                for (int ni = 0; ni < 8; ni++)
                    mma16816(acc[mi][ni], af[mi], &bf[ni >> 1][(ni & 1) * 2]);
            }
        }

        if (++s_cur == STAGES) s_cur = 0;
    }

    // Epilogue
    const int l4 = lane >> 2;
    const int l2 = (lane & 3) * 2;
    #pragma unroll
    for (int ni = 0; ni < 8; ni++) {
        const int col = n0 + warp_n * 64 + ni * 8 + l2;
        const float2 bv = *reinterpret_cast<const float2*>(&bias[col]);
        #pragma unroll
        for (int mi = 0; mi < 4; mi++) {
            const int row = m0 + warp_m * 64 + mi * 16 + l4;
            float2 v0, v1;
            v0.x = acc[mi][ni][0] + bv.x;
            v0.y = acc[mi][ni][1] + bv.y;
            v1.x = acc[mi][ni][2] + bv.x;
            v1.y = acc[mi][ni][3] + bv.y;
            *reinterpret_cast<float2*>(&C[(size_t)row * N + col]) = v0;
            *reinterpret_cast<float2*>(&C[(size_t)(row + 8) * N + col]) = v1;
        }
    }
}

// ---------------- launch ----------------

extern "C" void kernel_launch(void* const* d_in, const int* in_sizes, int n_in,
                              void* d_out, int out_size) {
    const float* x    = (const float*)d_in[0];
    const float* w    = (const float*)d_in[1];
    const float* bias = (const float*)d_in[2];
    const float* sw   = (const float*)d_in[3];
    const int*   idx  = (const int*)d_in[4];
    float* out = (float*)d_out;

    const int N = in_sizes[2];        // 4096
    const int K = in_sizes[1] / N;    // 4096
    const int M = in_sizes[0] / K;    // 8192
    const int nnz = in_sizes[3];      // 262144

    static bool attr_done = false;
    if (!attr_done) {
        cudaFuncSetAttribute(gemm_kernel,
                             cudaFuncAttributeMaxDynamicSharedMemorySize, SMEM_TOTAL);
        attr_done = true;
    }

    prep_wconv_kernel<<<1024, 256>>>(w, (N * K) / 4);
    prep_scatter_kernel<<<(nnz + 255) / 256, 256>>>(sw, idx, idx + nnz, nnz, K);
    prep_xh_kernel<<<2048, 256>>>(x, (M / 4) * K);

    dim3 grid(N / BN, M / BM);   // (32, 64)
    gemm_kernel<<<grid, 128, SMEM_TOTAL>>>(bias, out, N);
}